// round 17
// baseline (speedup 1.0000x reference)
#include <cuda_runtime.h>

namespace {

constexpr int Wd  = 512;
constexpr int Hd  = 512;
constexpr int TH  = 16;           // output rows per CTA
constexpr int VW  = 528;          // padded vbuf width (8 zero cols each side)
constexpr int NT  = 256;
constexpr int WIN = TH + 14;      // 30-row input window

__device__ __forceinline__ unsigned long long pack2(float lo, float hi) {
    unsigned long long r;
    asm("mov.b64 %0, {%1, %2};" : "=l"(r) : "f"(lo), "f"(hi));
    return r;
}
__device__ __forceinline__ void fma2(unsigned long long& d,
                                     unsigned long long a,
                                     unsigned long long b) {
    asm("fma.rn.f32x2 %0, %1, %2, %0;" : "+l"(d) : "l"(a), "l"(b));
}
__host__ __device__ constexpr int widx(int j) { return j < 8 ? j : 14 - j; }

union F4 {
    float4 f;
    unsigned long long u[2];
    float s[4];
};

__global__ void __launch_bounds__(NT, 4)
gauss_kernel(const float* __restrict__ x, const float* __restrict__ sigma,
             float* __restrict__ out, int C)
{
    __shared__ float vbuf[TH * VW];   // 33792 B -> 4 CTAs/SM

    const int strip = blockIdx.x;
    const int ch    = blockIdx.y;
    const int b     = blockIdx.z;
    const int tid   = threadIdx.x;
    const int r0    = strip * TH;

    // ---- zero-fill column halos (words [0,8) and [520,528) per row) ----
    if (tid < 64) {
        const int row = tid >> 2;
        const int q   = tid & 3;
        const int cc  = (q < 2) ? q * 4 : 520 + (q - 2) * 4;
        *reinterpret_cast<float4*>(&vbuf[row * VW + cc]) =
            make_float4(0.f, 0.f, 0.f, 0.f);
    }

    // ---- symmetric 1D Gaussian weights (8 distinct), packed broadcast ----
    const float sg  = sigma[b];
    const float inv = 1.0f / (2.0f * sg * sg + 1e-8f);
    float w[8];
    float s = 0.0f;
#pragma unroll
    for (int i = 0; i < 8; ++i) {
        const float a = (float)(7 - i);
        w[i] = __expf(-a * a * inv);
        s += (i < 7) ? 2.0f * w[i] : w[i];
    }
    const float rs = 1.0f / s;
    unsigned long long wp[8];
#pragma unroll
    for (int i = 0; i < 8; ++i) { w[i] *= rs; wp[i] = pack2(w[i], w[i]); }

    const size_t img = (size_t)(b * C + ch) * (Hd * Wd);
    const float* __restrict__ xp = x + img;
    float* __restrict__       op = out + img;

    // ================= Stage 1: vertical, global -> vbuf =================
    // thread: 2 cols x 16 rows; 30-row sliding input window
    {
        const int c0 = tid * 2;
        const int rbase = r0 - 7;

        unsigned long long acc[TH];
#pragma unroll
        for (int o = 0; o < TH; ++o) acc[o] = 0ull;

        if (rbase >= 0 && rbase + WIN - 1 < Hd) {
            const float* p = xp + (size_t)rbase * Wd + c0;
#pragma unroll
            for (int rr = 0; rr < WIN; ++rr) {
                const unsigned long long v =
                    *reinterpret_cast<const unsigned long long*>(p + rr * Wd);
#pragma unroll
                for (int o = 0; o < TH; ++o) {
                    const int j = rr - o;
                    if (j >= 0 && j < 15) fma2(acc[o], v, wp[widx(j)]);
                }
            }
        } else {
            const float* colp = xp + c0;
#pragma unroll
            for (int rr = 0; rr < WIN; ++rr) {
                const int gr = rbase + rr;
                if ((unsigned)gr < (unsigned)Hd) {
                    const unsigned long long v =
                        *reinterpret_cast<const unsigned long long*>(
                            colp + (size_t)gr * Wd);
#pragma unroll
                    for (int o = 0; o < TH; ++o) {
                        const int j = rr - o;
                        if (j >= 0 && j < 15) fma2(acc[o], v, wp[widx(j)]);
                    }
                }
            }
        }
#pragma unroll
        for (int o = 0; o < TH; ++o)
            *reinterpret_cast<unsigned long long*>(&vbuf[o * VW + 8 + c0]) =
                acc[o];
    }
    __syncthreads();

    // ================= Stage 2: horizontal, vbuf -> global =================
    // thread: 4-col chunk x 8 rows. Even-s input pairs come directly from
    // LDS.128 register pairs (no pack); only 9 odd-s pairs are packed.
    // Row pointers advance incrementally (no per-row IMAD chains).
    {
        const int chunk = tid & 127;
        const int rsel  = tid >> 7;
        const int gc0   = chunk * 4;

        const float* rp = &vbuf[8 + gc0] + rsel * VW;
        float* po = op + (size_t)(r0 + rsel) * Wd + gc0;

#pragma unroll
        for (int t = 0; t < 8; ++t) {
            F4 v[5];
#pragma unroll
            for (int k = 0; k < 5; ++k)
                v[k].f = *reinterpret_cast<const float4*>(rp - 8 + 4 * k);

            // odd-s pairs O[k] = (f[2k+1], f[2k+2]), k = 0..8
            unsigned long long O[9];
#pragma unroll
            for (int k = 0; k < 9; ++k) {
                const int i0 = 2 * k + 1;
                const int i1 = 2 * k + 2;
                O[k] = pack2(v[i0 >> 2].s[i0 & 3], v[i1 >> 2].s[i1 & 3]);
            }

            unsigned long long ap0 = 0ull, ap1 = 0ull;
#pragma unroll
            for (int sidx = 1; sidx <= 17; ++sidx) {
                const unsigned long long P =
                    (sidx & 1) ? O[(sidx - 1) >> 1]
                               : v[sidx >> 2].u[(sidx >> 1) & 1];
                if (sidx <= 15) fma2(ap0, P, wp[widx(sidx - 1)]);
                if (sidx >= 3)  fma2(ap1, P, wp[widx(sidx - 3)]);
            }
            *reinterpret_cast<ulonglong2*>(po) = make_ulonglong2(ap0, ap1);

            rp += 2 * VW;
            po += 2 * Wd;
        }
    }
}

}  // namespace

extern "C" void kernel_launch(void* const* d_in, const int* in_sizes, int n_in,
                              void* d_out, int out_size) {
    const float* x     = (const float*)d_in[0];
    const float* sigma = (const float*)d_in[1];
    float* out         = (float*)d_out;

    const int B = in_sizes[1];                      // 32
    const int C = in_sizes[0] / (B * Hd * Wd);      // 3

    dim3 grid(Hd / TH, C, B);                       // 32 x 3 x 32 = 3072
    gauss_kernel<<<grid, NT>>>(x, sigma, out, C);
}